// round 16
// baseline (speedup 1.0000x reference)
#include <cuda_runtime.h>
#include <cuda_fp16.h>

#define SMEM_BYTES 230592  // 147456 wt + 81920 stage + 512 osm + 704 btile

namespace {

// ---------- device scratch ----------
__device__ __half   g_wpack[3][786432];
__device__ float    g_yctr[512 * 1536];
__device__ __half   g_s0h[2][512 * 512];
__device__ __half   g_s1h[2][512 * 512];
__device__ float    g_fcpart[512 * 64];
__device__ unsigned g_bar[4096];

// ---------- helpers ----------
__device__ __forceinline__ unsigned su32(const void* p) {
  return (unsigned)__cvta_generic_to_shared(p);
}
__device__ __forceinline__ void cp16(unsigned d, const void* s) {
  asm volatile("cp.async.cg.shared.global [%0], [%1], 16;\n" :: "r"(d), "l"(s));
}
__device__ __forceinline__ void cpcommit() { asm volatile("cp.async.commit_group;\n"); }
template <int N> __device__ __forceinline__ void cpwait() {
  asm volatile("cp.async.wait_group %0;\n" :: "n"(N));
}
__device__ __forceinline__ void ldsm4(unsigned& r0, unsigned& r1, unsigned& r2,
                                      unsigned& r3, unsigned a) {
  asm volatile("ldmatrix.sync.aligned.m8n8.x4.shared.b16 {%0,%1,%2,%3}, [%4];\n"
               : "=r"(r0), "=r"(r1), "=r"(r2), "=r"(r3) : "r"(a));
}
__device__ __forceinline__ void mma16816(float* c, unsigned a0, unsigned a1,
                                         unsigned a2, unsigned a3,
                                         unsigned b0, unsigned b1) {
  asm volatile(
      "mma.sync.aligned.m16n8k16.row.col.f32.f16.f16.f32 "
      "{%0,%1,%2,%3},{%4,%5,%6,%7},{%8,%9},{%0,%1,%2,%3};\n"
      : "+f"(c[0]), "+f"(c[1]), "+f"(c[2]), "+f"(c[3])
      : "r"(a0), "r"(a1), "r"(a2), "r"(a3), "r"(b0), "r"(b1));
}
__device__ __forceinline__ float sigm(float x) {
  float t, r;
  asm("ex2.approx.f32 %0, %1;" : "=f"(t) : "f"(-1.4426950408889634f * x));
  asm("rcp.approx.f32 %0, %1;" : "=f"(r) : "f"(1.0f + t));
  return r;
}
__device__ __forceinline__ float tanh_(float x) {
  x = fminf(fmaxf(x, -15.f), 15.f);
  float t, r;
  asm("ex2.approx.f32 %0, %1;" : "=f"(t) : "f"(-2.8853900817779268f * x));
  asm("rcp.approx.f32 %0, %1;" : "=f"(r) : "f"(1.0f + t));
  return (1.0f - t) * r;
}
__device__ __forceinline__ void bar_arrive(unsigned* ctr) {
  __syncthreads();
  if (threadIdx.x == 0)
    asm volatile("red.release.gpu.global.add.u32 [%0], 1;" :: "l"(ctr) : "memory");
}
__device__ __forceinline__ void bar_wait(unsigned* ctr) {
  if (threadIdx.x == 0) {
    unsigned v;
    do {
      asm volatile("ld.acquire.gpu.global.u32 %0, [%1];" : "=r"(v) : "l"(ctr) : "memory");
    } while (v < 32u);
  }
  __syncthreads();
}

// ---------- prep kernels (identical to R13/R14) ----------
__global__ void prep_zero() {
  unsigned i = blockIdx.x * 256u + threadIdx.x;
  if (i < 4096u) g_bar[i] = 0u;
}

__global__ void prep_pack(const float* __restrict__ whh1,
                          const float* __restrict__ wih2,
                          const float* __restrict__ whh2) {
  unsigned t = blockIdx.x * 256u + threadIdx.x;
  if (t >= 589824u) return;
  unsigned lane = t & 31u, kt = (t >> 5) & 31u, nt = (t >> 10) & 1u;
  unsigned g = (t >> 11) % 3u, hs = (t / 6144u) & 31u, gm = t / 196608u;
  const float* W = (gm == 0) ? whh1 : (gm == 1 ? wih2 : whh2);
  int j = (int)(g * 512u + hs * 16u + nt * 8u + (lane >> 2));
  int k = (int)(kt * 16u + (lane & 3u) * 2u);
  const float* wr = W + (size_t)j * 512;
  __half* dst = g_wpack[gm] + (size_t)hs * 24576u +
                ((((g * 2u + nt) * 16u + (kt >> 1)) * 32u + lane) * 8u +
                 (kt & 1u) * 4u);
  *(__half2*)(dst)     = __floats2half2_rn(wr[k], wr[k + 1]);
  *(__half2*)(dst + 2) = __floats2half2_rn(wr[k + 8], wr[k + 9]);
}

__global__ void prep_yctr(const float* __restrict__ y,
                          const float* __restrict__ wih1,
                          const float* __restrict__ bih1) {
  __shared__ float ys[127];
  int b = blockIdx.x;
  for (int c = threadIdx.x; c < 127; c += blockDim.x) ys[c] = y[b * 127 + c];
  __syncthreads();
  for (int j = threadIdx.x; j < 1536; j += blockDim.x) {
    const float* wr = wih1 + (size_t)j * 128 + 1;
    float s = bih1[j];
#pragma unroll 4
    for (int c = 0; c < 127; c++) s += ys[c] * wr[c];
    g_yctr[(size_t)b * 1536 + j] = s;
  }
}

// ---------- staging: warp-private, chunk = 16 rows x 32 k, pitch 80 ----------
__device__ __forceinline__ void stage_chunk(const __half* __restrict__ Ag,
                                            unsigned wst, int mt, int lane,
                                            int ch) {
  if (ch < 16) {
    unsigned db = wst + (unsigned)((ch & 3) * 1280);
    const __half* s = Ag + ch * 32;
#pragma unroll
    for (int i = 0; i < 2; i++) {
      int idx = lane * 2 + i, rr = idx >> 2, seg = idx & 3;
      cp16(db + (unsigned)(rr * 80 + seg * 16),
           s + (mt * 16 + rr) * 512 + seg * 8);
    }
  }
  cpcommit();
}
__device__ __forceinline__ void gemm_prestage(const __half* __restrict__ Ag,
                                              unsigned wst, int mt, int lane) {
  stage_chunk(Ag, wst, mt, lane, 0);
  stage_chunk(Ag, wst, mt, lane, 1);
  stage_chunk(Ag, wst, mt, lane, 2);
}

// ---------- single GEMM: C[3][4] = A(16 own rows) @ W(nt-half 3x8)^T ----------
template <bool PRESTAGED>
__device__ __forceinline__ void gemm_slice(const __half* __restrict__ Ag,
                                           const unsigned* __restrict__ wsmu,
                                           unsigned wst, int mt, int nt,
                                           int lane, float (&C)[3][4]) {
#pragma unroll
  for (int g = 0; g < 3; g++)
#pragma unroll
    for (int e = 0; e < 4; e++) C[g][e] = 0.f;
  if (!PRESTAGED) gemm_prestage(Ag, wst, mt, lane);
  const unsigned arow = wst + (unsigned)((lane & 15) * 80 + (lane >> 4) * 16);
  for (int ch = 0; ch < 16; ch++) {
    stage_chunk(Ag, wst, mt, lane, ch + 3);
    cpwait<3>();
    __syncwarp();
    unsigned ab = arow + (unsigned)((ch & 3) * 1280);
    uint4 bv[3];
#pragma unroll
    for (int g = 0; g < 3; g++)
      bv[g] = *reinterpret_cast<const uint4*>(
          wsmu + ((((g * 2 + nt) * 16 + ch) * 32 + lane) << 2));
    unsigned x0, x1, x2, x3, y0, y1, y2, y3;
    ldsm4(x0, x1, x2, x3, ab);
    ldsm4(y0, y1, y2, y3, ab + 32);
#pragma unroll
    for (int g = 0; g < 3; g++) {
      mma16816(C[g], x0, x1, x2, x3, bv[g].x, bv[g].y);
      mma16816(C[g], y0, y1, y2, y3, bv[g].z, bv[g].w);
    }
  }
}

// ---------- dual GEMM: one A stream, two B slices (single-load Q) ----------
__device__ __forceinline__ void gemm_dual(const __half* __restrict__ Ag,
                                          const unsigned* __restrict__ wsmP,
                                          const unsigned* __restrict__ wsmQ,
                                          unsigned wst, int mt, int nt,
                                          int lane, float (&CP)[3][4],
                                          float (&CQ)[3][4]) {
#pragma unroll
  for (int g = 0; g < 3; g++)
#pragma unroll
    for (int e = 0; e < 4; e++) { CP[g][e] = 0.f; CQ[g][e] = 0.f; }
  gemm_prestage(Ag, wst, mt, lane);
  const unsigned arow = wst + (unsigned)((lane & 15) * 80 + (lane >> 4) * 16);
  for (int ch = 0; ch < 16; ch++) {
    stage_chunk(Ag, wst, mt, lane, ch + 3);
    cpwait<3>();
    __syncwarp();
    unsigned ab = arow + (unsigned)((ch & 3) * 1280);
    unsigned widx[3];
#pragma unroll
    for (int g = 0; g < 3; g++)
      widx[g] = (((g * 2 + nt) * 16 + ch) * 32 + lane) << 2;
    unsigned x0, x1, x2, x3, y0, y1, y2, y3;
    ldsm4(x0, x1, x2, x3, ab);
    ldsm4(y0, y1, y2, y3, ab + 32);
    uint4 bv[3];
#pragma unroll
    for (int g = 0; g < 3; g++)
      bv[g] = *reinterpret_cast<const uint4*>(wsmP + widx[g]);
#pragma unroll
    for (int g = 0; g < 3; g++) {
      mma16816(CP[g], x0, x1, x2, x3, bv[g].x, bv[g].y);
      mma16816(CP[g], y0, y1, y2, y3, bv[g].z, bv[g].w);
    }
#pragma unroll
    for (int g = 0; g < 3; g++)
      bv[g] = *reinterpret_cast<const uint4*>(wsmQ + widx[g]);
#pragma unroll
    for (int g = 0; g < 3; g++) {
      mma16816(CQ[g], x0, x1, x2, x3, bv[g].x, bv[g].y);
      mma16816(CQ[g], y0, y1, y2, y3, bv[g].z, bv[g].w);
    }
  }
}

// ---------- main persistent kernel: 512 threads, 16 warps ----------
// warp w: m-tile mt=w>>1 (16 rows), n-half nt=w&1 (8 h-cols)
__global__ void __launch_bounds__(512, 1)
gen_main(const float* __restrict__ z1, const float* __restrict__ y,
         const float* __restrict__ x, const float* __restrict__ hid1,
         const float* __restrict__ wih1, const float* __restrict__ bhh1g,
         const float* __restrict__ bih2g, const float* __restrict__ bhh2g,
         const float* __restrict__ wfc, const float* __restrict__ bfcp,
         float* __restrict__ dout) {
  extern __shared__ unsigned char smem[];
  __half* wsm = (__half*)smem;                   // 147456 B
  const unsigned stage0 = su32(smem + 147456);   // 16 warps x 4 bufs x 1280 B
  float* osm = (float*)(smem + 229376);          // 128 f32
  float* btile = (float*)(smem + 229888);        // 176 f32
  const unsigned* wsmu = (const unsigned*)wsm;

  const int cta = blockIdx.x, bt = cta >> 5, hs = cta & 31;
  const int tid = threadIdx.x, w = tid >> 5, lane = tid & 31;
  const int mt = w >> 1, nt = w & 1;
  const unsigned wst = stage0 + (unsigned)(w * 5120);

  // weight slices -> SMEM
  {
    unsigned dbase = su32(wsm);
    for (int i = tid; i < 9216; i += 512) {
      int gm = i / 3072, q = i - gm * 3072;
      cp16(dbase + (unsigned)((gm * 24576 + q * 8) * 2),
           g_wpack[gm] + (size_t)hs * 24576 + q * 8);
    }
    cpcommit();
  }
  // bias tile -> SMEM
  if (tid < 16) {
    int j = tid, jj = hs * 16 + j;
    btile[j]       = bhh1g[jj];
    btile[16 + j]  = bhh1g[512 + jj];
    btile[32 + j]  = bhh1g[1024 + jj];
    btile[48 + j]  = wih1[(size_t)jj * 128];
    btile[64 + j]  = wih1[(size_t)(512 + jj) * 128];
    btile[80 + j]  = wih1[(size_t)(1024 + jj) * 128];
    btile[96 + j]  = bih2g[jj] + bhh2g[jj];
    btile[112 + j] = bih2g[512 + jj] + bhh2g[512 + jj];
    btile[128 + j] = bih2g[1024 + jj];
    btile[144 + j] = bhh2g[1024 + jj];
    btile[160 + j] = wfc[jj];
  }

  const int h0 = (lane & 3) * 2;
  const int jj0 = hs * 16 + nt * 8 + h0;  // global h of thread col 0
  const int brow = mt * 16 + (lane >> 2); // local batch row (second = +8)
  const float bfc = bfcp[0];

  // loop-invariant ycontrib + fp32 states (R11-validated mapping)
  float yc[3][2][2], s0f[2][2], s1f[2][2];
#pragma unroll
  for (int bh = 0; bh < 2; bh++) {
    int gb = bt * 128 + brow + bh * 8;
    const float* yb = g_yctr + (size_t)gb * 1536 + jj0;
#pragma unroll
    for (int g = 0; g < 3; g++) {
      yc[g][bh][0] = yb[g * 512];
      yc[g][bh][1] = yb[g * 512 + 1];
    }
#pragma unroll
    for (int i = 0; i < 2; i++) {
      int gh = jj0 + i;
      s0f[bh][i] = (gh < 385) ? z1[(size_t)gb * 385 + gh]
                              : y[(size_t)gb * 127 + (gh - 385)];
      s1f[bh][i] = hid1[(size_t)gb * 512 + gh];
    }
    *(__half2*)&g_s0h[0][(size_t)gb * 512 + jj0] =
        __floats2half2_rn(s0f[bh][0], s0f[bh][1]);
    *(__half2*)&g_s1h[0][(size_t)gb * 512 + jj0] =
        __floats2half2_rn(s1f[bh][0], s1f[bh][1]);
  }
  if (tid < 128) osm[tid] = x[bt * 128 + tid];
  cpwait<0>();
  __syncthreads();

  unsigned* barp = &g_bar[bt * 1024];
  bar_arrive(barp + 512);
  bar_wait(barp + 512);

  float Cg1[3][4], Cg2[3][4], Ci[3][4];

  // pre-loop: gh1 for t=0
  gemm_slice<false>(g_s0h[0] + (size_t)bt * 65536, wsmu, wst, mt, nt, lane, Cg1);

  for (int t = 0; t < 256; t++) {
    const int pb = t & 1, nb = pb ^ 1;
    const __half* s1p = g_s1h[pb] + (size_t)bt * 65536;

    // head for t-1 (after bar2[t-1]); prestage gh2 first to hide its L2 fill
    if (t > 0) bar_wait(barp + (t - 1) * 2 + 1);
    gemm_prestage(s1p, wst, mt, lane);
    if (t > 0 && tid < 128) {
      const float* fp = &g_fcpart[(size_t)(bt * 128 + tid) * 64];
      float s = bfc;
#pragma unroll 16
      for (int k = 0; k < 64; k++) s += __ldcg(fp + k);
      float o = fmaxf(s, 0.f);
      osm[tid] = o;
      if (hs == 0) dout[(size_t)(bt * 128 + tid) * 256 + (t - 1)] = o;
    }
    __syncthreads();

    // ---- cell-1 -> s0' ----
    {
      float ob[2] = {osm[brow], osm[brow + 8]};
#pragma unroll
      for (int bh = 0; bh < 2; bh++) {
#pragma unroll
        for (int i = 0; i < 2; i++) {
          int e = bh * 2 + i;
          int hl = nt * 8 + h0 + i;
          float gr = yc[0][bh][i] + ob[bh] * btile[48 + hl] + Cg1[0][e] + btile[hl];
          float gz = yc[1][bh][i] + ob[bh] * btile[64 + hl] + Cg1[1][e] + btile[16 + hl];
          float gn = yc[2][bh][i] + ob[bh] * btile[80 + hl];
          float r = sigm(gr), z = sigm(gz);
          float n = tanh_(gn + r * (Cg1[2][e] + btile[32 + hl]));
          s0f[bh][i] = (1.f - z) * n + z * s0f[bh][i];
        }
        int gb = bt * 128 + brow + bh * 8;
        *(__half2*)&g_s0h[nb][(size_t)gb * 512 + jj0] =
            __floats2half2_rn(s0f[bh][0], s0f[bh][1]);
      }
    }
    bar_arrive(barp + t * 2);  // s0' published

    // ---- gh2 = s1 @ whh2^T (slice 2; prestaged; hides bar1) ----
    gemm_slice<true>(s1p, wsmu + 24576, wst, mt, nt, lane, Cg2);

    bar_wait(barp + t * 2);  // all s0' visible

    // ---- fused: gi2 (slice 1) + gh1[t+1] (slice 0), one A pass ----
    gemm_dual(g_s0h[nb] + (size_t)bt * 65536, wsmu + 12288, wsmu, wst, mt, nt,
              lane, Ci, Cg1);

    // ---- cell-2 -> s1', fc partials ----
    {
      const int hl0 = nt * 8 + h0;
#pragma unroll
      for (int bh = 0; bh < 2; bh++) {
#pragma unroll
        for (int i = 0; i < 2; i++) {
          int e = bh * 2 + i;
          int hl = hl0 + i;
          float r = sigm(Ci[0][e] + Cg2[0][e] + btile[96 + hl]);
          float z = sigm(Ci[1][e] + Cg2[1][e] + btile[112 + hl]);
          float n = tanh_(Ci[2][e] + btile[128 + hl] +
                          r * (Cg2[2][e] + btile[144 + hl]));
          s1f[bh][i] = (1.f - z) * n + z * s1f[bh][i];
        }
        int gb = bt * 128 + brow + bh * 8;
        *(__half2*)&g_s1h[nb][(size_t)gb * 512 + jj0] =
            __floats2half2_rn(s1f[bh][0], s1f[bh][1]);
        float p = s1f[bh][0] * btile[160 + hl0] + s1f[bh][1] * btile[161 + hl0];
        p += __shfl_xor_sync(0xffffffffu, p, 1);
        p += __shfl_xor_sync(0xffffffffu, p, 2);
        if ((lane & 3) == 0)
          __stcg(&g_fcpart[(size_t)gb * 64 + hs * 2 + nt], p);
      }
    }
    bar_arrive(barp + t * 2 + 1);  // s1' + fcpart published
  }

  // final head (o[255])
  bar_wait(barp + 255 * 2 + 1);
  if (tid < 128 && hs == 0) {
    const float* fp = &g_fcpart[(size_t)(bt * 128 + tid) * 64];
    float s = bfc;
#pragma unroll 16
    for (int k = 0; k < 64; k++) s += __ldcg(fp + k);
    dout[(size_t)(bt * 128 + tid) * 256 + 255] = fmaxf(s, 0.f);
  }
}

}  // namespace

extern "C" void kernel_launch(void* const* d_in, const int* in_sizes, int n_in,
                              void* d_out, int out_size) {
  const float* z1   = (const float*)d_in[0];
  const float* y    = (const float*)d_in[1];
  const float* x    = (const float*)d_in[2];
  const float* h1   = (const float*)d_in[3];
  const float* wih1 = (const float*)d_in[4];
  const float* whh1 = (const float*)d_in[5];
  const float* bih1 = (const float*)d_in[6];
  const float* bhh1 = (const float*)d_in[7];
  const float* wih2 = (const float*)d_in[8];
  const float* whh2 = (const float*)d_in[9];
  const float* bih2 = (const float*)d_in[10];
  const float* bhh2 = (const float*)d_in[11];
  const float* wfc  = (const float*)d_in[12];
  const float* bfc  = (const float*)d_in[13];

  cudaFuncSetAttribute(gen_main, cudaFuncAttributeMaxDynamicSharedMemorySize,
                       SMEM_BYTES);

  prep_zero<<<16, 256>>>();
  prep_pack<<<2304, 256>>>(whh1, wih2, whh2);
  prep_yctr<<<512, 256>>>(y, wih1, bih1);
  gen_main<<<128, 512, SMEM_BYTES>>>(z1, y, x, h1, wih1, bhh1, bih2, bhh2,
                                     wfc, bfc, (float*)d_out);
}